// round 15
// baseline (speedup 1.0000x reference)
#include <cuda_runtime.h>
#include <cuda_fp16.h>
#include <math.h>

#define HSZ 1024
#define STOT 8192
#define NHEAD 16
#define HDIM 64
#define SPN 4
#define SCHUNK 2048

__device__ __half g_q[STOT * HSZ];
__device__ __half g_k[STOT * HSZ];
__device__ __half g_v[STOT * HSZ];
__device__ __half g_ctx[STOT * HSZ];
__device__ __half g_xh[STOT * HSZ];
__device__ __half g_wh[4][HSZ * HSZ];   // fp16 weights, [K][N] layout

// ---------------- helpers ----------------
__device__ __forceinline__ unsigned f22u(float a, float b) {
    __half2 h = __floats2half2_rn(a, b);
    return *reinterpret_cast<unsigned*>(&h);
}
__device__ __forceinline__ unsigned ex2h2(unsigned x) {
    unsigned y; asm("ex2.approx.f16x2 %0, %1;" : "=r"(y) : "r"(x)); return y;
}
__device__ __forceinline__ void mma_f16(float* c, unsigned a0, unsigned a1,
                                        unsigned a2, unsigned a3,
                                        unsigned b0, unsigned b1) {
    asm volatile(
        "mma.sync.aligned.m16n8k16.row.col.f32.f16.f16.f32 "
        "{%0,%1,%2,%3},{%4,%5,%6,%7},{%8,%9},{%0,%1,%2,%3};"
        : "+f"(c[0]), "+f"(c[1]), "+f"(c[2]), "+f"(c[3])
        : "r"(a0), "r"(a1), "r"(a2), "r"(a3), "r"(b0), "r"(b1));
}
__device__ __forceinline__ void ldsm_x4(unsigned& r0, unsigned& r1,
                                        unsigned& r2, unsigned& r3, unsigned a) {
    asm volatile("ldmatrix.sync.aligned.m8n8.x4.shared.b16 {%0,%1,%2,%3},[%4];"
                 : "=r"(r0), "=r"(r1), "=r"(r2), "=r"(r3) : "r"(a));
}
__device__ __forceinline__ void ldsm_x4t(unsigned& r0, unsigned& r1,
                                         unsigned& r2, unsigned& r3, unsigned a) {
    asm volatile(
        "ldmatrix.sync.aligned.m8n8.x4.trans.shared.b16 {%0,%1,%2,%3},[%4];"
        : "=r"(r0), "=r"(r1), "=r"(r2), "=r"(r3) : "r"(a));
}
__device__ __forceinline__ void cp16(unsigned dst, const void* src) {
    asm volatile("cp.async.cg.shared.global [%0],[%1],16;" :: "r"(dst), "l"(src));
}
#define CP_COMMIT() asm volatile("cp.async.commit_group;")
#define CP_WAIT(n)  asm volatile("cp.async.wait_group %0;" :: "n"(n))

// ---------------- fp32 -> fp16 converts ----------------
__global__ __launch_bounds__(256) void f32to16(const float* __restrict__ s,
                                               __half* __restrict__ d, int n) {
    const int i = (blockIdx.x * 256 + threadIdx.x) * 8;
    if (i < n) {
        float4 v0 = *(const float4*)(s + i);
        float4 v1 = *(const float4*)(s + i + 4);
        uint4 o;
        o.x = f22u(v0.x, v0.y); o.y = f22u(v0.z, v0.w);
        o.z = f22u(v1.x, v1.y); o.w = f22u(v1.z, v1.w);
        *(uint4*)(d + i) = o;
    }
}
__global__ __launch_bounds__(256) void wconv4(
    const float* __restrict__ w0, const float* __restrict__ w1,
    const float* __restrict__ w2, const float* __restrict__ w3,
    __half* __restrict__ d) {
    const float* s = (blockIdx.y == 0) ? w0 : (blockIdx.y == 1) ? w1
                    : (blockIdx.y == 2) ? w2 : w3;
    const int i = (blockIdx.x * 256 + threadIdx.x) * 8;
    float4 v0 = *(const float4*)(s + i);
    float4 v1 = *(const float4*)(s + i + 4);
    uint4 o;
    o.x = f22u(v0.x, v0.y); o.y = f22u(v0.z, v0.w);
    o.z = f22u(v1.x, v1.y); o.w = f22u(v1.z, v1.w);
    *(uint4*)(d + (size_t)blockIdx.y * HSZ * HSZ + i) = o;
}

// ---------------------------------------------------------------------------
// FP16 mma.sync GEMM, BK=64, 2-stage cp.async ring (unchanged from R10).
// ---------------------------------------------------------------------------
#define PA2 72
#define PB 136
#define A_B2 (128 * PA2 * 2)
#define STG2_B ((128 * PA2 + 64 * PB) * 2)
#define G3_SMEM (2 * STG2_B)
#define NSTEP2 16

template <int QKV, typename OutT>
__global__ __launch_bounds__(256, 2) void gemm3(
    const __half* __restrict__ A,
    const __half* __restrict__ B0, const __half* __restrict__ B1,
    const __half* __restrict__ B2,
    const float* __restrict__ bias0, const float* __restrict__ bias1,
    const float* __restrict__ bias2,
    OutT* __restrict__ C0, OutT* __restrict__ C1, OutT* __restrict__ C2,
    float scale0)
{
    extern __shared__ __half sm3[];
    const int tid = threadIdx.x;
    const int warp = tid >> 5, lane = tid & 31;
    const int g = lane >> 2, q = lane & 3;
    const int wm = warp >> 2, wn = warp & 3;

    int sel = 0, bnx = blockIdx.x;
    if (QKV) { sel = blockIdx.x >> 3; bnx = blockIdx.x & 7; }
    const __half* B = (sel == 0) ? B0 : (sel == 1) ? B1 : B2;
    const float* bias = (sel == 0) ? bias0 : (sel == 1) ? bias1 : bias2;
    OutT* C = (sel == 0) ? C0 : (sel == 1) ? C1 : C2;
    const float scale = (sel == 0) ? scale0 : 1.f;

    const int bn = bnx * 128, bm = blockIdx.y * 128;

    float acc[16][4];
#pragma unroll
    for (int i = 0; i < 16; i++)
#pragma unroll
        for (int j = 0; j < 4; j++) acc[i][j] = 0.f;

    const unsigned smU = (unsigned)__cvta_generic_to_shared(sm3);
    const unsigned aRel =
        ((wm * 64 + (lane & 15)) * PA2 + ((lane & 16) >> 1)) * 2;
    const unsigned bRel = A_B2 + ((lane & 15) * PB + wn * 32) * 2 + (lane & 16);

#define G3LD64(s, stgU) do {                                                  \
    _Pragma("unroll")                                                         \
    for (int i_ = 0; i_ < 4; i_++) {                                          \
        int idx_ = tid + i_ * 256;                                            \
        int ar_ = idx_ >> 3, ac_ = (idx_ & 7) * 8;                            \
        cp16((stgU) + (ar_ * PA2 + ac_) * 2,                                  \
             A + (size_t)(bm + ar_) * HSZ + (s) * 64 + ac_);                  \
        int br_ = idx_ >> 4, bc_ = (idx_ & 15) * 8;                           \
        cp16((stgU) + A_B2 + (br_ * PB + bc_) * 2,                            \
             B + (size_t)((s) * 64 + br_) * HSZ + bn + bc_);                  \
    }                                                                         \
} while (0)

    G3LD64(0, smU);
    CP_COMMIT();

#pragma unroll 1
    for (int s = 0; s < NSTEP2; s++) {
        CP_WAIT(0);
        __syncthreads();
        if (s + 1 < NSTEP2) {
            G3LD64(s + 1, smU + ((s + 1) & 1) * STG2_B);
            CP_COMMIT();
        }
        const unsigned stg = smU + (s & 1) * STG2_B;
        const unsigned aCur = stg + aRel, bCur = stg + bRel;
#pragma unroll
        for (int kt = 0; kt < 4; kt++) {
            unsigned a[4][4];
#pragma unroll
            for (int mt = 0; mt < 4; mt++)
                ldsm_x4(a[mt][0], a[mt][1], a[mt][2], a[mt][3],
                        aCur + mt * 16 * PA2 * 2 + kt * 32);
#pragma unroll
            for (int ntp = 0; ntp < 2; ntp++) {
                unsigned p0, p1, p2, p3;
                ldsm_x4t(p0, p1, p2, p3, bCur + kt * 16 * PB * 2 + ntp * 32);
#pragma unroll
                for (int mt = 0; mt < 4; mt++) {
                    mma_f16(acc[mt * 4 + 2 * ntp], a[mt][0], a[mt][1],
                            a[mt][2], a[mt][3], p0, p1);
                    mma_f16(acc[mt * 4 + 2 * ntp + 1], a[mt][0], a[mt][1],
                            a[mt][2], a[mt][3], p2, p3);
                }
            }
        }
    }

#pragma unroll
    for (int mt = 0; mt < 4; mt++) {
        const int row = bm + wm * 64 + mt * 16 + g;
#pragma unroll
        for (int nt = 0; nt < 4; nt++) {
            const int col = bn + wn * 32 + nt * 8 + 2 * q;
            const float bx = bias[col], by = bias[col + 1];
            float c0 = (acc[mt * 4 + nt][0] + bx) * scale;
            float c1 = (acc[mt * 4 + nt][1] + by) * scale;
            float c2 = (acc[mt * 4 + nt][2] + bx) * scale;
            float c3 = (acc[mt * 4 + nt][3] + by) * scale;
            if (sizeof(OutT) == 4) {
                *(float2*)&((float*)C)[(size_t)row * HSZ + col] =
                    make_float2(c0, c1);
                *(float2*)&((float*)C)[(size_t)(row + 8) * HSZ + col] =
                    make_float2(c2, c3);
            } else {
                unsigned u0 = f22u(c0, c1), u1 = f22u(c2, c3);
                *(unsigned*)&((__half*)C)[(size_t)row * HSZ + col] = u0;
                *(unsigned*)&((__half*)C)[(size_t)(row + 8) * HSZ + col] = u1;
            }
        }
    }
}

// ---------------------------------------------------------------------------
// FP16 mma.sync ring attention v6 = R12 math + software-pipelined score MMAs:
// S(g+1) issues during exp(g)'s cvt/MUFU latency window, filling the tensor
// pipe. Two score buffers, fully-unrolled group loop. K-tile 64 (R12 best).
// ---------------------------------------------------------------------------
#define PH 72
#define QTILE_H (128 * PH)
#define KTILE_H (64 * PH)
#define ATT_SMEM_BYTES ((QTILE_H + 4 * KTILE_H) * 2)
#define ONE2 0x3C003C00u

__global__ __launch_bounds__(128, 2) void attn_f16(
    const __half* __restrict__ Q, const __half* __restrict__ K,
    const __half* __restrict__ V, __half* __restrict__ ctx)
{
    extern __shared__ __half smp[];
    __half* Qs = smp;
    __half* Ks = Qs + QTILE_H;
    __half* Vs = Ks + 2 * KTILE_H;

    const int tid = threadIdx.x;
    const int lane = tid & 31;
    const int warp = tid >> 5;
    const int g = lane >> 2, q = lane & 3;
    const int rowB = warp * 32;
    const int qb = blockIdx.x, h = blockIdx.y, r = blockIdx.z;

    const unsigned QsU = (unsigned)__cvta_generic_to_shared(Qs);
    const unsigned KsU = (unsigned)__cvta_generic_to_shared(Ks);
    const unsigned VsU = (unsigned)__cvta_generic_to_shared(Vs);

    const size_t qrow0 = (size_t)(r * SCHUNK + qb * 128);

    // Q tile (128 rows) + KV tile 0 -> smem
#pragma unroll
    for (int i = 0; i < 8; i++) {
        const int idx = tid + i * 128;
        const int row = idx >> 3, c16 = (idx & 7) * 8;
        cp16(QsU + (row * PH + c16) * 2,
             Q + (qrow0 + row) * HSZ + h * HDIM + c16);
    }
#pragma unroll
    for (int i = 0; i < 4; i++) {
        const int idx = tid + i * 128;
        const int key = idx >> 3, c16 = (idx & 7) * 8;
        const size_t src = (size_t)key * HSZ + h * HDIM + c16;
        cp16(KsU + (key * PH + c16) * 2, K + src);
        cp16(VsU + (key * PH + c16) * 2, V + src);
    }
    CP_COMMIT();
    CP_WAIT(0);
    __syncthreads();

    // hoist Q fragments: 2 m-blocks x 4 k-chunks x 4 regs
    unsigned Qf[2][4][4];
#pragma unroll
    for (int mb = 0; mb < 2; mb++) {
        const unsigned qA =
            QsU + ((rowB + mb * 16 + (lane & 15)) * PH + ((lane & 16) >> 1)) * 2;
#pragma unroll
        for (int kt = 0; kt < 4; kt++)
            ldsm_x4(Qf[mb][kt][0], Qf[mb][kt][1], Qf[mb][kt][2], Qf[mb][kt][3],
                    qA + kt * 32);
    }

    const unsigned kX4 =
        (((lane & 7) + ((lane & 16) >> 1)) * PH + (lane & 8)) * 2;
    const unsigned vX4 = ((lane & 15) * PH) * 2 + (lane & 16);

    float accO[2][8][4];
#pragma unroll
    for (int mb = 0; mb < 2; mb++)
#pragma unroll
        for (int i = 0; i < 8; i++)
#pragma unroll
            for (int j = 0; j < 4; j++) accO[mb][i][j] = 0.f;

// compute S of group 'grp' into score buffer 'dst' [2][2][4]
#define COMPUTE_S(dst, grp) do {                                              \
    _Pragma("unroll")                                                         \
    for (int mb_ = 0; mb_ < 2; mb_++)                                         \
        _Pragma("unroll")                                                     \
        for (int nt_ = 0; nt_ < 2; nt_++)                                     \
            _Pragma("unroll")                                                 \
            for (int j_ = 0; j_ < 4; j_++) dst[mb_][nt_][j_] = 0.f;           \
    _Pragma("unroll")                                                         \
    for (int kt_ = 0; kt_ < 4; kt_++) {                                       \
        unsigned b0_, b1_, b2_, b3_;                                          \
        ldsm_x4(b0_, b1_, b2_, b3_,                                           \
                Kbuf + kX4 + (grp) * 16 * PH * 2 + kt_ * 32);                 \
        _Pragma("unroll")                                                     \
        for (int mb_ = 0; mb_ < 2; mb_++) {                                   \
            mma_f16(dst[mb_][0], Qf[mb_][kt_][0], Qf[mb_][kt_][1],            \
                    Qf[mb_][kt_][2], Qf[mb_][kt_][3], b0_, b1_);              \
            mma_f16(dst[mb_][1], Qf[mb_][kt_][0], Qf[mb_][kt_][1],            \
                    Qf[mb_][kt_][2], Qf[mb_][kt_][3], b2_, b3_);              \
        }                                                                     \
    }                                                                         \
} while (0)

    for (int c = 0; c < SPN; c++) {
        float lsum[2][4];
        float O[2][8][4];
#pragma unroll
        for (int mb = 0; mb < 2; mb++) {
#pragma unroll
            for (int j = 0; j < 4; j++) lsum[mb][j] = 0.f;
#pragma unroll
            for (int i = 0; i < 8; i++)
#pragma unroll
                for (int j = 0; j < 4; j++) O[mb][i][j] = 0.f;
        }

#pragma unroll 1
        for (int kb = 0; kb < SCHUNK / 64; kb++) {
            const int t = c * 32 + kb;
            CP_WAIT(0);
            __syncthreads();
            if (t + 1 < SPN * 32) {
                const unsigned kb1 = KsU + ((t + 1) & 1) * KTILE_H * 2;
                const unsigned vb1 = VsU + ((t + 1) & 1) * KTILE_H * 2;
#pragma unroll
                for (int i = 0; i < 4; i++) {
                    const int idx = tid + i * 128;
                    const int key = idx >> 3, c16 = (idx & 7) * 8;
                    const size_t src =
                        (size_t)((t + 1) * 64 + key) * HSZ + h * HDIM + c16;
                    cp16(kb1 + (key * PH + c16) * 2, K + src);
                    cp16(vb1 + (key * PH + c16) * 2, V + src);
                }
                CP_COMMIT();
            }

            const unsigned Kbuf = KsU + (t & 1) * KTILE_H * 2;
            const unsigned Vbuf = VsU + (t & 1) * KTILE_H * 2;

            // software-pipelined groups: S(g+1) overlaps exp(g)
            float scb[2][2][2][4];  // [buf][mb][nt][4]
            COMPUTE_S(scb[0], 0);
#pragma unroll
            for (int grp = 0; grp < 4; grp++) {
                const int cur = grp & 1;
                // ---- P = exp2(S) in fp16x2 -> A-fragments; l += P@ones ----
                unsigned aF[2][4];
#pragma unroll
                for (int mb = 0; mb < 2; mb++) {
                    aF[mb][0] = ex2h2(f22u(scb[cur][mb][0][0], scb[cur][mb][0][1]));
                    aF[mb][1] = ex2h2(f22u(scb[cur][mb][0][2], scb[cur][mb][0][3]));
                    aF[mb][2] = ex2h2(f22u(scb[cur][mb][1][0], scb[cur][mb][1][1]));
                    aF[mb][3] = ex2h2(f22u(scb[cur][mb][1][2], scb[cur][mb][1][3]));
                }
                // fill the exp latency window with next group's QK mmas
                if (grp < 3) COMPUTE_S(scb[cur ^ 1], grp + 1);
#pragma unroll
                for (int mb = 0; mb < 2; mb++)
                    mma_f16(lsum[mb], aF[mb][0], aF[mb][1], aF[mb][2],
                            aF[mb][3], ONE2, ONE2);
                // ---- O += P @ V ----
#pragma unroll
                for (int ntp = 0; ntp < 4; ntp++) {
                    unsigned v0, v1, v2, v3;
                    ldsm_x4t(v0, v1, v2, v3,
                             Vbuf + vX4 + grp * 16 * PH * 2 + ntp * 32);
#pragma unroll
                    for (int mb = 0; mb < 2; mb++) {
                        mma_f16(O[mb][2 * ntp], aF[mb][0], aF[mb][1],
                                aF[mb][2], aF[mb][3], v0, v1);
                        mma_f16(O[mb][2 * ntp + 1], aF[mb][0], aF[mb][1],
                                aF[mb][2], aF[mb][3], v2, v3);
                    }
                }
            }
        }

        // chunk end: every lane holds full row sums in its lsum C-fragment
#pragma unroll
        for (int mb = 0; mb < 2; mb++) {
            const float inv0 = 0.25f / lsum[mb][0];
            const float inv1 = 0.25f / lsum[mb][2];
#pragma unroll
            for (int nt = 0; nt < 8; nt++) {
                accO[mb][nt][0] = fmaf(O[mb][nt][0], inv0, accO[mb][nt][0]);
                accO[mb][nt][1] = fmaf(O[mb][nt][1], inv0, accO[mb][nt][1]);
                accO[mb][nt][2] = fmaf(O[mb][nt][2], inv1, accO[mb][nt][2]);
                accO[mb][nt][3] = fmaf(O[mb][nt][3], inv1, accO[mb][nt][3]);
            }
        }
    }

    // write ctx (fp16, layout [s, h*64+d])
#pragma unroll
    for (int mb = 0; mb < 2; mb++)
#pragma unroll
        for (int nt = 0; nt < 8; nt++) {
            const int col = h * HDIM + nt * 8 + 2 * q;
            const size_t row0 = qrow0 + rowB + mb * 16 + g;
            unsigned u0 = f22u(accO[mb][nt][0], accO[mb][nt][1]);
            unsigned u1 = f22u(accO[mb][nt][2], accO[mb][nt][3]);
            *(unsigned*)&ctx[row0 * HSZ + col] = u0;
            *(unsigned*)&ctx[(row0 + 8) * HSZ + col] = u1;
        }
}

// ---------------------------------------------------------------------------
extern "C" void kernel_launch(void* const* d_in, const int* in_sizes, int n_in,
                              void* d_out, int out_size)
{
    const float* X  = (const float*)d_in[0];
    const float* Wq = (const float*)d_in[1];
    const float* bq = (const float*)d_in[2];
    const float* Wk = (const float*)d_in[3];
    const float* bk = (const float*)d_in[4];
    const float* Wv = (const float*)d_in[5];
    const float* bv = (const float*)d_in[6];
    const float* Wo = (const float*)d_in[7];
    const float* bo = (const float*)d_in[8];
    float* out = (float*)d_out;

    __half *qp, *kp, *vp, *cp, *xh, *wh;
    cudaGetSymbolAddress((void**)&qp, g_q);
    cudaGetSymbolAddress((void**)&kp, g_k);
    cudaGetSymbolAddress((void**)&vp, g_v);
    cudaGetSymbolAddress((void**)&cp, g_ctx);
    cudaGetSymbolAddress((void**)&xh, g_xh);
    cudaGetSymbolAddress((void**)&wh, g_wh);

    cudaFuncSetAttribute(attn_f16,
                         cudaFuncAttributeMaxDynamicSharedMemorySize,
                         ATT_SMEM_BYTES);
    cudaFuncSetAttribute(gemm3<1, __half>,
                         cudaFuncAttributeMaxDynamicSharedMemorySize, G3_SMEM);
    cudaFuncSetAttribute(gemm3<0, float>,
                         cudaFuncAttributeMaxDynamicSharedMemorySize, G3_SMEM);

    f32to16<<<STOT * HSZ / (8 * 256), 256>>>(X, xh, STOT * HSZ);
    wconv4<<<dim3(HSZ * HSZ / (8 * 256), 4), 256>>>(Wq, Wk, Wv, Wo, wh);

    const float QSCALE = 0.125f * 1.44269504088896f;  // 1/sqrt(64) * log2(e)

    gemm3<1, __half><<<dim3(24, 64), 256, G3_SMEM>>>(
        xh, wh, wh + HSZ * HSZ, wh + 2 * HSZ * HSZ,
        bq, bk, bv, qp, kp, vp, QSCALE);

    attn_f16<<<dim3(SCHUNK / 128, NHEAD, SPN), 128, ATT_SMEM_BYTES>>>(
        qp, kp, vp, cp);

    gemm3<0, float><<<dim3(8, 64), 256, G3_SMEM>>>(
        cp, wh + 3 * HSZ * HSZ, (const __half*)0, (const __half*)0,
        bo, (const float*)0, (const float*)0,
        out, (float*)0, (float*)0, 1.f);
}

// round 17
// speedup vs baseline: 1.5871x; 1.5871x over previous
#include <cuda_runtime.h>
#include <cuda_fp16.h>
#include <math.h>

#define HSZ 1024
#define STOT 8192
#define NHEAD 16
#define HDIM 64
#define SPN 4
#define SCHUNK 2048

__device__ __half g_q[STOT * HSZ];
__device__ __half g_k[STOT * HSZ];
__device__ __half g_v[STOT * HSZ];
__device__ __half g_ctx[STOT * HSZ];
__device__ __half g_xh[STOT * HSZ];
__device__ __half g_wh[4][HSZ * HSZ];          // fp16 weights, [K][N]
__device__ float  g_part[4][STOT * HSZ];       // per-chunk fp32 partials

// ---------------- helpers ----------------
__device__ __forceinline__ unsigned f22u(float a, float b) {
    __half2 h = __floats2half2_rn(a, b);
    return *reinterpret_cast<unsigned*>(&h);
}
__device__ __forceinline__ unsigned ex2h2(unsigned x) {
    unsigned y; asm("ex2.approx.f16x2 %0, %1;" : "=r"(y) : "r"(x)); return y;
}
__device__ __forceinline__ void mma_f16(float* c, unsigned a0, unsigned a1,
                                        unsigned a2, unsigned a3,
                                        unsigned b0, unsigned b1) {
    asm volatile(
        "mma.sync.aligned.m16n8k16.row.col.f32.f16.f16.f32 "
        "{%0,%1,%2,%3},{%4,%5,%6,%7},{%8,%9},{%0,%1,%2,%3};"
        : "+f"(c[0]), "+f"(c[1]), "+f"(c[2]), "+f"(c[3])
        : "r"(a0), "r"(a1), "r"(a2), "r"(a3), "r"(b0), "r"(b1));
}
__device__ __forceinline__ void ldsm_x4(unsigned& r0, unsigned& r1,
                                        unsigned& r2, unsigned& r3, unsigned a) {
    asm volatile("ldmatrix.sync.aligned.m8n8.x4.shared.b16 {%0,%1,%2,%3},[%4];"
                 : "=r"(r0), "=r"(r1), "=r"(r2), "=r"(r3) : "r"(a));
}
__device__ __forceinline__ void ldsm_x4t(unsigned& r0, unsigned& r1,
                                         unsigned& r2, unsigned& r3, unsigned a) {
    asm volatile(
        "ldmatrix.sync.aligned.m8n8.x4.trans.shared.b16 {%0,%1,%2,%3},[%4];"
        : "=r"(r0), "=r"(r1), "=r"(r2), "=r"(r3) : "r"(a));
}
__device__ __forceinline__ void cp16(unsigned dst, const void* src) {
    asm volatile("cp.async.cg.shared.global [%0],[%1],16;" :: "r"(dst), "l"(src));
}
#define CP_COMMIT() asm volatile("cp.async.commit_group;")
#define CP_WAIT(n)  asm volatile("cp.async.wait_group %0;" :: "n"(n))

// ---------------- fp32 -> fp16 converts ----------------
__global__ __launch_bounds__(256) void f32to16(const float* __restrict__ s,
                                               __half* __restrict__ d, int n) {
    const int i = (blockIdx.x * 256 + threadIdx.x) * 8;
    if (i < n) {
        float4 v0 = *(const float4*)(s + i);
        float4 v1 = *(const float4*)(s + i + 4);
        uint4 o;
        o.x = f22u(v0.x, v0.y); o.y = f22u(v0.z, v0.w);
        o.z = f22u(v1.x, v1.y); o.w = f22u(v1.z, v1.w);
        *(uint4*)(d + i) = o;
    }
}
__global__ __launch_bounds__(256) void wconv4(
    const float* __restrict__ w0, const float* __restrict__ w1,
    const float* __restrict__ w2, const float* __restrict__ w3,
    __half* __restrict__ d) {
    const float* s = (blockIdx.y == 0) ? w0 : (blockIdx.y == 1) ? w1
                    : (blockIdx.y == 2) ? w2 : w3;
    const int i = (blockIdx.x * 256 + threadIdx.x) * 8;
    float4 v0 = *(const float4*)(s + i);
    float4 v1 = *(const float4*)(s + i + 4);
    uint4 o;
    o.x = f22u(v0.x, v0.y); o.y = f22u(v0.z, v0.w);
    o.z = f22u(v1.x, v1.y); o.w = f22u(v1.z, v1.w);
    *(uint4*)(d + (size_t)blockIdx.y * HSZ * HSZ + i) = o;
}

// sum 4 fp32 partial buffers -> fp16 ctx
__global__ __launch_bounds__(256) void reduce4(const float* __restrict__ p,
                                               __half* __restrict__ d) {
    const size_t i = ((size_t)blockIdx.x * 256 + threadIdx.x) * 4;
    const size_t N = (size_t)STOT * HSZ;
    float4 a = *(const float4*)(p + i);
    float4 b = *(const float4*)(p + N + i);
    float4 c = *(const float4*)(p + 2 * N + i);
    float4 e = *(const float4*)(p + 3 * N + i);
    float s0 = a.x + b.x + c.x + e.x;
    float s1 = a.y + b.y + c.y + e.y;
    float s2 = a.z + b.z + c.z + e.z;
    float s3 = a.w + b.w + c.w + e.w;
    uint2 o;
    o.x = f22u(s0, s1);
    o.y = f22u(s2, s3);
    *(uint2*)(d + i) = o;
}

// ---------------------------------------------------------------------------
// FP16 mma.sync GEMM, BK=64, 2-stage cp.async ring (unchanged from R10).
// ---------------------------------------------------------------------------
#define PA2 72
#define PB 136
#define A_B2 (128 * PA2 * 2)
#define STG2_B ((128 * PA2 + 64 * PB) * 2)
#define G3_SMEM (2 * STG2_B)
#define NSTEP2 16

template <int QKV, typename OutT>
__global__ __launch_bounds__(256, 2) void gemm3(
    const __half* __restrict__ A,
    const __half* __restrict__ B0, const __half* __restrict__ B1,
    const __half* __restrict__ B2,
    const float* __restrict__ bias0, const float* __restrict__ bias1,
    const float* __restrict__ bias2,
    OutT* __restrict__ C0, OutT* __restrict__ C1, OutT* __restrict__ C2,
    float scale0)
{
    extern __shared__ __half sm3[];
    const int tid = threadIdx.x;
    const int warp = tid >> 5, lane = tid & 31;
    const int g = lane >> 2, q = lane & 3;
    const int wm = warp >> 2, wn = warp & 3;

    int sel = 0, bnx = blockIdx.x;
    if (QKV) { sel = blockIdx.x >> 3; bnx = blockIdx.x & 7; }
    const __half* B = (sel == 0) ? B0 : (sel == 1) ? B1 : B2;
    const float* bias = (sel == 0) ? bias0 : (sel == 1) ? bias1 : bias2;
    OutT* C = (sel == 0) ? C0 : (sel == 1) ? C1 : C2;
    const float scale = (sel == 0) ? scale0 : 1.f;

    const int bn = bnx * 128, bm = blockIdx.y * 128;

    float acc[16][4];
#pragma unroll
    for (int i = 0; i < 16; i++)
#pragma unroll
        for (int j = 0; j < 4; j++) acc[i][j] = 0.f;

    const unsigned smU = (unsigned)__cvta_generic_to_shared(sm3);
    const unsigned aRel =
        ((wm * 64 + (lane & 15)) * PA2 + ((lane & 16) >> 1)) * 2;
    const unsigned bRel = A_B2 + ((lane & 15) * PB + wn * 32) * 2 + (lane & 16);

#define G3LD64(s, stgU) do {                                                  \
    _Pragma("unroll")                                                         \
    for (int i_ = 0; i_ < 4; i_++) {                                          \
        int idx_ = tid + i_ * 256;                                            \
        int ar_ = idx_ >> 3, ac_ = (idx_ & 7) * 8;                            \
        cp16((stgU) + (ar_ * PA2 + ac_) * 2,                                  \
             A + (size_t)(bm + ar_) * HSZ + (s) * 64 + ac_);                  \
        int br_ = idx_ >> 4, bc_ = (idx_ & 15) * 8;                           \
        cp16((stgU) + A_B2 + (br_ * PB + bc_) * 2,                            \
             B + (size_t)((s) * 64 + br_) * HSZ + bn + bc_);                  \
    }                                                                         \
} while (0)

    G3LD64(0, smU);
    CP_COMMIT();

#pragma unroll 1
    for (int s = 0; s < NSTEP2; s++) {
        CP_WAIT(0);
        __syncthreads();
        if (s + 1 < NSTEP2) {
            G3LD64(s + 1, smU + ((s + 1) & 1) * STG2_B);
            CP_COMMIT();
        }
        const unsigned stg = smU + (s & 1) * STG2_B;
        const unsigned aCur = stg + aRel, bCur = stg + bRel;
#pragma unroll
        for (int kt = 0; kt < 4; kt++) {
            unsigned a[4][4];
#pragma unroll
            for (int mt = 0; mt < 4; mt++)
                ldsm_x4(a[mt][0], a[mt][1], a[mt][2], a[mt][3],
                        aCur + mt * 16 * PA2 * 2 + kt * 32);
#pragma unroll
            for (int ntp = 0; ntp < 2; ntp++) {
                unsigned p0, p1, p2, p3;
                ldsm_x4t(p0, p1, p2, p3, bCur + kt * 16 * PB * 2 + ntp * 32);
#pragma unroll
                for (int mt = 0; mt < 4; mt++) {
                    mma_f16(acc[mt * 4 + 2 * ntp], a[mt][0], a[mt][1],
                            a[mt][2], a[mt][3], p0, p1);
                    mma_f16(acc[mt * 4 + 2 * ntp + 1], a[mt][0], a[mt][1],
                            a[mt][2], a[mt][3], p2, p3);
                }
            }
        }
    }

#pragma unroll
    for (int mt = 0; mt < 4; mt++) {
        const int row = bm + wm * 64 + mt * 16 + g;
#pragma unroll
        for (int nt = 0; nt < 4; nt++) {
            const int col = bn + wn * 32 + nt * 8 + 2 * q;
            const float bx = bias[col], by = bias[col + 1];
            float c0 = (acc[mt * 4 + nt][0] + bx) * scale;
            float c1 = (acc[mt * 4 + nt][1] + by) * scale;
            float c2 = (acc[mt * 4 + nt][2] + bx) * scale;
            float c3 = (acc[mt * 4 + nt][3] + by) * scale;
            if (sizeof(OutT) == 4) {
                *(float2*)&((float*)C)[(size_t)row * HSZ + col] =
                    make_float2(c0, c1);
                *(float2*)&((float*)C)[(size_t)(row + 8) * HSZ + col] =
                    make_float2(c2, c3);
            } else {
                unsigned u0 = f22u(c0, c1), u1 = f22u(c2, c3);
                *(unsigned*)&((__half*)C)[(size_t)row * HSZ + col] = u0;
                *(unsigned*)&((__half*)C)[(size_t)(row + 8) * HSZ + col] = u1;
            }
        }
    }
}

// ---------------------------------------------------------------------------
// FP16 mma.sync ring attention v7 = R12 math, one (rank, chunk) per CTA.
// grid (16, NHEAD, 16): z = r*4 + chunk. accO eliminated -> fewer registers,
// __launch_bounds__(128,3) for 12 warps/SM; 4096 CTAs kill tail-wave waste.
// Writes fp32 partial 0.25*O/l to g_part[chunk]; reduce4 sums into ctx.
// ---------------------------------------------------------------------------
#define PH 72
#define QTILE_H (128 * PH)
#define KTILE_H (64 * PH)
#define ATT_SMEM_BYTES ((QTILE_H + 4 * KTILE_H) * 2)
#define ONE2 0x3C003C00u

__global__ __launch_bounds__(128, 3) void attn_f16(
    const __half* __restrict__ Q, const __half* __restrict__ K,
    const __half* __restrict__ V, float* __restrict__ part)
{
    extern __shared__ __half smp[];
    __half* Qs = smp;
    __half* Ks = Qs + QTILE_H;
    __half* Vs = Ks + 2 * KTILE_H;

    const int tid = threadIdx.x;
    const int lane = tid & 31;
    const int warp = tid >> 5;
    const int g = lane >> 2, q = lane & 3;
    const int rowB = warp * 32;
    const int qb = blockIdx.x, h = blockIdx.y;
    const int r = blockIdx.z >> 2, ck = blockIdx.z & 3;

    const unsigned QsU = (unsigned)__cvta_generic_to_shared(Qs);
    const unsigned KsU = (unsigned)__cvta_generic_to_shared(Ks);
    const unsigned VsU = (unsigned)__cvta_generic_to_shared(Vs);

    const size_t qrow0 = (size_t)(r * SCHUNK + qb * 128);
    const size_t krow0 = (size_t)(ck * SCHUNK);

    // Q tile + KV tile 0 -> smem
#pragma unroll
    for (int i = 0; i < 8; i++) {
        const int idx = tid + i * 128;
        const int row = idx >> 3, c16 = (idx & 7) * 8;
        cp16(QsU + (row * PH + c16) * 2,
             Q + (qrow0 + row) * HSZ + h * HDIM + c16);
    }
#pragma unroll
    for (int i = 0; i < 4; i++) {
        const int idx = tid + i * 128;
        const int key = idx >> 3, c16 = (idx & 7) * 8;
        const size_t src = (krow0 + key) * HSZ + h * HDIM + c16;
        cp16(KsU + (key * PH + c16) * 2, K + src);
        cp16(VsU + (key * PH + c16) * 2, V + src);
    }
    CP_COMMIT();
    CP_WAIT(0);
    __syncthreads();

    // hoist Q fragments: 2 m-blocks x 4 k-chunks x 4 regs
    unsigned Qf[2][4][4];
#pragma unroll
    for (int mb = 0; mb < 2; mb++) {
        const unsigned qA =
            QsU + ((rowB + mb * 16 + (lane & 15)) * PH + ((lane & 16) >> 1)) * 2;
#pragma unroll
        for (int kt = 0; kt < 4; kt++)
            ldsm_x4(Qf[mb][kt][0], Qf[mb][kt][1], Qf[mb][kt][2], Qf[mb][kt][3],
                    qA + kt * 32);
    }

    const unsigned kX4 =
        (((lane & 7) + ((lane & 16) >> 1)) * PH + (lane & 8)) * 2;
    const unsigned vX4 = ((lane & 15) * PH) * 2 + (lane & 16);

    float lsum[2][4];
    float O[2][8][4];
#pragma unroll
    for (int mb = 0; mb < 2; mb++) {
#pragma unroll
        for (int j = 0; j < 4; j++) lsum[mb][j] = 0.f;
#pragma unroll
        for (int i = 0; i < 8; i++)
#pragma unroll
            for (int j = 0; j < 4; j++) O[mb][i][j] = 0.f;
    }

#pragma unroll 1
    for (int kb = 0; kb < SCHUNK / 64; kb++) {
        CP_WAIT(0);
        __syncthreads();
        if (kb + 1 < SCHUNK / 64) {
            const unsigned kb1 = KsU + ((kb + 1) & 1) * KTILE_H * 2;
            const unsigned vb1 = VsU + ((kb + 1) & 1) * KTILE_H * 2;
#pragma unroll
            for (int i = 0; i < 4; i++) {
                const int idx = tid + i * 128;
                const int key = idx >> 3, c16 = (idx & 7) * 8;
                const size_t src =
                    (krow0 + (kb + 1) * 64 + key) * HSZ + h * HDIM + c16;
                cp16(kb1 + (key * PH + c16) * 2, K + src);
                cp16(vb1 + (key * PH + c16) * 2, V + src);
            }
            CP_COMMIT();
        }

        const unsigned Kbuf = KsU + (kb & 1) * KTILE_H * 2;
        const unsigned Vbuf = VsU + (kb & 1) * KTILE_H * 2;

#pragma unroll
        for (int grp = 0; grp < 4; grp++) {
            const unsigned gOff = grp * 16 * PH * 2;
            // ---- S = Q @ K^T for 16 keys ----
            float sc[2][2][4];
#pragma unroll
            for (int mb = 0; mb < 2; mb++)
#pragma unroll
                for (int nt = 0; nt < 2; nt++)
#pragma unroll
                    for (int j = 0; j < 4; j++) sc[mb][nt][j] = 0.f;
#pragma unroll
            for (int kt = 0; kt < 4; kt++) {
                unsigned b0, b1, b2, b3;
                ldsm_x4(b0, b1, b2, b3, Kbuf + kX4 + gOff + kt * 32);
#pragma unroll
                for (int mb = 0; mb < 2; mb++) {
                    mma_f16(sc[mb][0], Qf[mb][kt][0], Qf[mb][kt][1],
                            Qf[mb][kt][2], Qf[mb][kt][3], b0, b1);
                    mma_f16(sc[mb][1], Qf[mb][kt][0], Qf[mb][kt][1],
                            Qf[mb][kt][2], Qf[mb][kt][3], b2, b3);
                }
            }
            // ---- P = exp2(S) fp16x2 -> A-fragments; l += P @ ones ----
            unsigned aF[2][4];
#pragma unroll
            for (int mb = 0; mb < 2; mb++) {
                aF[mb][0] = ex2h2(f22u(sc[mb][0][0], sc[mb][0][1]));
                aF[mb][1] = ex2h2(f22u(sc[mb][0][2], sc[mb][0][3]));
                aF[mb][2] = ex2h2(f22u(sc[mb][1][0], sc[mb][1][1]));
                aF[mb][3] = ex2h2(f22u(sc[mb][1][2], sc[mb][1][3]));
                mma_f16(lsum[mb], aF[mb][0], aF[mb][1], aF[mb][2],
                        aF[mb][3], ONE2, ONE2);
            }
            // ---- O += P @ V ----
#pragma unroll
            for (int ntp = 0; ntp < 4; ntp++) {
                unsigned v0, v1, v2, v3;
                ldsm_x4t(v0, v1, v2, v3, Vbuf + vX4 + gOff + ntp * 32);
#pragma unroll
                for (int mb = 0; mb < 2; mb++) {
                    mma_f16(O[mb][2 * ntp], aF[mb][0], aF[mb][1],
                            aF[mb][2], aF[mb][3], v0, v1);
                    mma_f16(O[mb][2 * ntp + 1], aF[mb][0], aF[mb][1],
                            aF[mb][2], aF[mb][3], v2, v3);
                }
            }
        }
    }

    // write fp32 partial 0.25*O/l to g_part[ck]; layout [s, h*64+d]
    float* pc = part + (size_t)ck * STOT * HSZ;
#pragma unroll
    for (int mb = 0; mb < 2; mb++) {
        const float inv0 = 0.25f / lsum[mb][0];
        const float inv1 = 0.25f / lsum[mb][2];
#pragma unroll
        for (int nt = 0; nt < 8; nt++) {
            const int col = h * HDIM + nt * 8 + 2 * q;
            const size_t row0 = qrow0 + rowB + mb * 16 + g;
            *(float2*)&pc[row0 * HSZ + col] =
                make_float2(O[mb][nt][0] * inv0, O[mb][nt][1] * inv0);
            *(float2*)&pc[(row0 + 8) * HSZ + col] =
                make_float2(O[mb][nt][2] * inv1, O[mb][nt][3] * inv1);
        }
    }
}

// ---------------------------------------------------------------------------
extern "C" void kernel_launch(void* const* d_in, const int* in_sizes, int n_in,
                              void* d_out, int out_size)
{
    const float* X  = (const float*)d_in[0];
    const float* Wq = (const float*)d_in[1];
    const float* bq = (const float*)d_in[2];
    const float* Wk = (const float*)d_in[3];
    const float* bk = (const float*)d_in[4];
    const float* Wv = (const float*)d_in[5];
    const float* bv = (const float*)d_in[6];
    const float* Wo = (const float*)d_in[7];
    const float* bo = (const float*)d_in[8];
    float* out = (float*)d_out;

    __half *qp, *kp, *vp, *cp, *xh, *wh;
    float* pp;
    cudaGetSymbolAddress((void**)&qp, g_q);
    cudaGetSymbolAddress((void**)&kp, g_k);
    cudaGetSymbolAddress((void**)&vp, g_v);
    cudaGetSymbolAddress((void**)&cp, g_ctx);
    cudaGetSymbolAddress((void**)&xh, g_xh);
    cudaGetSymbolAddress((void**)&wh, g_wh);
    cudaGetSymbolAddress((void**)&pp, g_part);

    cudaFuncSetAttribute(attn_f16,
                         cudaFuncAttributeMaxDynamicSharedMemorySize,
                         ATT_SMEM_BYTES);
    cudaFuncSetAttribute(gemm3<1, __half>,
                         cudaFuncAttributeMaxDynamicSharedMemorySize, G3_SMEM);
    cudaFuncSetAttribute(gemm3<0, float>,
                         cudaFuncAttributeMaxDynamicSharedMemorySize, G3_SMEM);

    f32to16<<<STOT * HSZ / (8 * 256), 256>>>(X, xh, STOT * HSZ);
    wconv4<<<dim3(HSZ * HSZ / (8 * 256), 4), 256>>>(Wq, Wk, Wv, Wo, wh);

    const float QSCALE = 0.125f * 1.44269504088896f;  // 1/sqrt(64) * log2(e)

    gemm3<1, __half><<<dim3(24, 64), 256, G3_SMEM>>>(
        xh, wh, wh + HSZ * HSZ, wh + 2 * HSZ * HSZ,
        bq, bk, bv, qp, kp, vp, QSCALE);

    attn_f16<<<dim3(SCHUNK / 128, NHEAD, 4 * SPN), 128, ATT_SMEM_BYTES>>>(
        qp, kp, vp, pp);
    reduce4<<<STOT * HSZ / (4 * 256), 256>>>(pp, cp);

    gemm3<0, float><<<dim3(8, 64), 256, G3_SMEM>>>(
        cp, wh + 3 * HSZ * HSZ, (const __half*)0, (const __half*)0,
        bo, (const float*)0, (const float*)0,
        out, (float*)0, (float*)0, 1.f);
}